// round 1
// baseline (speedup 1.0000x reference)
#include <cuda_runtime.h>
#include <math.h>

// Problem constants
#define N_NODES 102400
#define N_EDGES 819200
#define N_GRAPH 512
#define NPG     200
#define BB      8
#define TT      64
#define DD      128
#define NH      4
#define DH      32
#define NL      4
#define HID     64

// ---------------- scratch (device globals; no allocation) ----------------
__device__ __align__(256) float g_deg [N_NODES];            // deg -> dinv (in place)
__device__ __align__(256) float g_agg1[N_NODES * 2];
__device__ __align__(256) float g_h   [N_NODES * HID];      // h1 then h2
__device__ __align__(256) float g_agg [N_NODES * HID];      // agg2 then agg3
__device__ __align__(256) float g_seq [BB * TT * DD];
__device__ __align__(256) float g_qkv [BB * TT * 3 * DD];
__device__ __align__(256) float g_att [BB * TT * DD];
__device__ __align__(256) float g_proj[BB * TT * DD];
__device__ __align__(256) float g_ffn [BB * TT * 4 * DD];

__device__ __forceinline__ void red_add_v4(float* p, float4 v) {
    asm volatile("red.global.add.v4.f32 [%0], {%1,%2,%3,%4};"
                 :: "l"(p), "f"(v.x), "f"(v.y), "f"(v.z), "f"(v.w) : "memory");
}

// ---------------- degree / normalization ----------------
__global__ void k_deg_init() {
    int i = blockIdx.x * blockDim.x + threadIdx.x;
    if (i < N_NODES) g_deg[i] = 1.0f;          // self loop
}
__global__ void k_deg_acc(const int* __restrict__ dst) {
    int e = blockIdx.x * blockDim.x + threadIdx.x;
    if (e < N_EDGES) atomicAdd(&g_deg[dst[e]], 1.0f);
}
__global__ void k_rsqrt() {
    int i = blockIdx.x * blockDim.x + threadIdx.x;
    if (i < N_NODES) g_deg[i] = rsqrtf(g_deg[i]);   // now dinv
}

// ---------------- GCN layer 1 (aggregate dim=2, then transform) ----------------
__global__ void k_agg1_init(const float* __restrict__ x) {
    int i = blockIdx.x * blockDim.x + threadIdx.x;
    if (i < N_NODES) {
        float di = g_deg[i]; float s = di * di;
        g_agg1[2 * i]     = x[2 * i]     * s;
        g_agg1[2 * i + 1] = x[2 * i + 1] * s;
    }
}
__global__ void k_agg1_edges(const float* __restrict__ x,
                             const int* __restrict__ src, const int* __restrict__ dst) {
    int e = blockIdx.x * blockDim.x + threadIdx.x;
    if (e < N_EDGES) {
        int s = src[e], d = dst[e];
        float nr = g_deg[s] * g_deg[d];
        atomicAdd(&g_agg1[2 * d],     x[2 * s]     * nr);
        atomicAdd(&g_agg1[2 * d + 1], x[2 * s + 1] * nr);
    }
}
// h1 = LN(relu(agg1 @ W1 + b1)) ; 4 nodes per 256-thread block
__global__ void k_l1(const float* __restrict__ W, const float* __restrict__ b,
                     const float* __restrict__ ga, const float* __restrict__ be) {
    int tid  = threadIdx.x;
    int node = blockIdx.x * 4 + (tid >> 6);
    int j    = tid & 63;
    float a0 = g_agg1[node * 2], a1 = g_agg1[node * 2 + 1];
    float v  = fmaxf(a0 * W[j] + a1 * W[64 + j] + b[j], 0.0f);
    float s = v, q = v * v;
    #pragma unroll
    for (int o = 16; o >= 1; o >>= 1) {
        s += __shfl_xor_sync(0xffffffffu, s, o);
        q += __shfl_xor_sync(0xffffffffu, q, o);
    }
    __shared__ float ss[8], sq[8];
    int w = tid >> 5;
    if ((tid & 31) == 0) { ss[w] = s; sq[w] = q; }
    __syncthreads();
    float S = ss[w] + ss[w ^ 1];
    float Q = sq[w] + sq[w ^ 1];
    float m = S * (1.0f / 64.0f);
    float var = Q * (1.0f / 64.0f) - m * m;
    float inv = rsqrtf(var + 1e-5f);
    g_h[node * 64 + j] = (v - m) * inv * ga[j] + be[j];
}

// ---------------- 64-wide aggregation (self loop + edges) ----------------
__global__ void k_selfinit() {     // g_agg[i] = g_h[i] * dinv[i]^2
    int t = blockIdx.x * blockDim.x + threadIdx.x;
    if (t < N_NODES * 16) {
        int i = t >> 4;
        float di = g_deg[i]; float sc = di * di;
        float4 v = reinterpret_cast<const float4*>(g_h)[t];
        v.x *= sc; v.y *= sc; v.z *= sc; v.w *= sc;
        reinterpret_cast<float4*>(g_agg)[t] = v;
    }
}
__global__ void k_edges64(const int* __restrict__ src, const int* __restrict__ dst) {
    int t = blockIdx.x * blockDim.x + threadIdx.x;
    if (t < N_EDGES * 16) {
        int e = t >> 4, q = t & 15;
        int s = src[e], d = dst[e];
        float nr = g_deg[s] * g_deg[d];
        float4 v = reinterpret_cast<const float4*>(g_h)[s * 16 + q];
        v.x *= nr; v.y *= nr; v.z *= nr; v.w *= nr;
        red_add_v4(&g_agg[d * 64 + q * 4], v);
    }
}

// ---------------- GCN layer 2 transform: h2 = LN(relu(agg @ W2 + b2)) ----------------
// 16 nodes per 256-thread block; thread computes 4 outputs (float4 W loads from smem)
__global__ void k_l2(const float* __restrict__ W, const float* __restrict__ b,
                     const float* __restrict__ ga, const float* __restrict__ be) {
    __shared__ float4 Ws[64 * 16];
    __shared__ float rows[16 * 64];
    __shared__ float bs[64], gs[64], bes[64];
    int tid = threadIdx.x;
    for (int i = tid; i < 1024; i += 256) Ws[i] = reinterpret_cast<const float4*>(W)[i];
    if (tid < 64) { bs[tid] = b[tid]; gs[tid] = ga[tid]; bes[tid] = be[tid]; }
    int base = blockIdx.x * 16 * 64;
    for (int i = tid; i < 1024; i += 256) rows[i] = g_agg[base + i];
    __syncthreads();

    int slot = tid >> 4, jg = tid & 15;
    const float* r = &rows[slot * 64];
    float a0 = 0, a1 = 0, a2 = 0, a3 = 0;
    #pragma unroll
    for (int k = 0; k < 64; k++) {
        float rv = r[k];
        float4 w = Ws[k * 16 + jg];
        a0 += rv * w.x; a1 += rv * w.y; a2 += rv * w.z; a3 += rv * w.w;
    }
    int j0 = jg * 4;
    float v0 = fmaxf(a0 + bs[j0],     0.f);
    float v1 = fmaxf(a1 + bs[j0 + 1], 0.f);
    float v2 = fmaxf(a2 + bs[j0 + 2], 0.f);
    float v3 = fmaxf(a3 + bs[j0 + 3], 0.f);
    float s = v0 + v1 + v2 + v3;
    float q = v0 * v0 + v1 * v1 + v2 * v2 + v3 * v3;
    #pragma unroll
    for (int o = 8; o >= 1; o >>= 1) {      // 16-thread group (stays within warp half)
        s += __shfl_xor_sync(0xffffffffu, s, o);
        q += __shfl_xor_sync(0xffffffffu, q, o);
    }
    float m   = s * (1.0f / 64.0f);
    float var = q * (1.0f / 64.0f) - m * m;
    float inv = rsqrtf(var + 1e-5f);
    float4 o4;
    o4.x = (v0 - m) * inv * gs[j0]     + bes[j0];
    o4.y = (v1 - m) * inv * gs[j0 + 1] + bes[j0 + 1];
    o4.z = (v2 - m) * inv * gs[j0 + 2] + bes[j0 + 2];
    o4.w = (v3 - m) * inv * gs[j0 + 3] + bes[j0 + 3];
    reinterpret_cast<float4*>(g_h)[(blockIdx.x * 16 + slot) * 16 + jg] = o4;
}

// ---------------- readout: emb = mean_g(agg3) @ W3 + b3 + PE -> g_seq ----------------
__global__ void k_graph_emb(const float* __restrict__ W3, const float* __restrict__ b3) {
    int gidx = blockIdx.x, t = threadIdx.x;   // 128 threads
    __shared__ float part[128];
    __shared__ float am[64];
    int j = t & 63, half = t >> 6;
    const float* base = &g_agg[(gidx * NPG + half * 100) * 64];
    float s = 0.f;
    for (int n = 0; n < 100; n++) s += base[n * 64 + j];
    part[t] = s;
    __syncthreads();
    if (t < 64) am[t] = (part[t] + part[t + 64]) * (1.0f / 200.0f);
    __syncthreads();
    float acc = b3[t];
    #pragma unroll
    for (int k = 0; k < 64; k++) acc += am[k] * W3[k * 128 + t];
    int ts = gidx & 63;                 // g = b*T + t_seq
    int i2 = t >> 1;
    float dv  = expf((float)(2 * i2) * (-9.210340371976184f / 128.0f));
    float ang = (float)ts * dv;
    float pe  = (t & 1) ? cosf(ang) : sinf(ang);
    g_seq[gidx * 128 + t] = acc + pe;
}

// ---------------- generic GEMM: C = A(MxK) @ B(NxK)^T + bias, opt relu ----------------
__global__ void k_gemm(const float* __restrict__ A, const float* __restrict__ B,
                       const float* __restrict__ bias, float* __restrict__ C,
                       int M, int N, int K, int relu) {
    __shared__ float As[64][17], Bs[64][17];
    int tx = threadIdx.x, ty = threadIdx.y;
    int tid = ty * 16 + tx;
    int m0 = blockIdx.y * 64, n0 = blockIdx.x * 64;
    float acc[4][4] = {};
    for (int k0 = 0; k0 < K; k0 += 16) {
        #pragma unroll
        for (int i = 0; i < 4; i++) {
            int idx = tid + i * 256;
            int r = idx >> 4, c = idx & 15;
            As[r][c] = A[(m0 + r) * K + k0 + c];
            Bs[r][c] = B[(n0 + r) * K + k0 + c];
        }
        __syncthreads();
        #pragma unroll
        for (int kk = 0; kk < 16; kk++) {
            float a[4], bb[4];
            #pragma unroll
            for (int i = 0; i < 4; i++) a[i]  = As[ty * 4 + i][kk];
            #pragma unroll
            for (int j = 0; j < 4; j++) bb[j] = Bs[tx * 4 + j][kk];
            #pragma unroll
            for (int i = 0; i < 4; i++)
                #pragma unroll
                for (int j = 0; j < 4; j++) acc[i][j] += a[i] * bb[j];
        }
        __syncthreads();
    }
    #pragma unroll
    for (int i = 0; i < 4; i++)
        #pragma unroll
        for (int j = 0; j < 4; j++) {
            float v = acc[i][j] + bias[n0 + tx * 4 + j];
            if (relu) v = fmaxf(v, 0.f);
            C[(m0 + ty * 4 + i) * N + n0 + tx * 4 + j] = v;
        }
}

// ---------------- attention: one (batch, head) per block, 64 threads ----------------
__global__ void k_attn() {
    int bh = blockIdx.x;
    int b = bh >> 2, h = bh & 3;
    int t = threadIdx.x;
    __shared__ float ks[2048], vs[2048];
    for (int idx = t; idx < 2048; idx += 64) {
        int tok = idx >> 5, d = idx & 31;
        const float* row = &g_qkv[(b * 64 + tok) * 384 + h * 32 + d];
        ks[idx] = row[128];
        vs[idx] = row[256];
    }
    float qr[32];
    #pragma unroll
    for (int d = 0; d < 32; d++) qr[d] = g_qkv[(b * 64 + t) * 384 + h * 32 + d];
    __syncthreads();
    float s[64];
    float mx = -1e30f;
    #pragma unroll 4
    for (int j = 0; j < 64; j++) {
        float a = 0.f;
        #pragma unroll
        for (int d = 0; d < 32; d++) a += qr[d] * ks[j * 32 + d];
        a *= 0.17677669529663687f;
        s[j] = a;
        mx = fmaxf(mx, a);
    }
    float sum = 0.f;
    #pragma unroll
    for (int j = 0; j < 64; j++) { s[j] = __expf(s[j] - mx); sum += s[j]; }
    float inv = 1.0f / sum;
    #pragma unroll 4
    for (int d = 0; d < 32; d++) {
        float o = 0.f;
        #pragma unroll
        for (int j = 0; j < 64; j++) o += s[j] * vs[j * 32 + d];
        g_att[(b * 64 + t) * 128 + h * 32 + d] = o * inv;
    }
}

// ---------------- residual + LN (seq = LN(seq + proj)) ----------------
__global__ void k_addln(const float* __restrict__ ga, const float* __restrict__ be) {
    int i = blockIdx.x, j = threadIdx.x;   // 128 threads
    float v = g_seq[i * 128 + j] + g_proj[i * 128 + j];
    float s = v, q = v * v;
    #pragma unroll
    for (int o = 16; o >= 1; o >>= 1) {
        s += __shfl_xor_sync(0xffffffffu, s, o);
        q += __shfl_xor_sync(0xffffffffu, q, o);
    }
    __shared__ float ss[4], sq[4];
    int w = j >> 5;
    if ((j & 31) == 0) { ss[w] = s; sq[w] = q; }
    __syncthreads();
    float S = ss[0] + ss[1] + ss[2] + ss[3];
    float Q = sq[0] + sq[1] + sq[2] + sq[3];
    float m = S * (1.0f / 128.0f);
    float var = Q * (1.0f / 128.0f) - m * m;
    float inv = rsqrtf(var + 1e-5f);
    g_seq[i * 128 + j] = (v - m) * inv * ga[j] + be[j];
}

// ---------------- pooled head ----------------
__global__ void k_head(const float* __restrict__ hW1, const float* __restrict__ hb1,
                       const float* __restrict__ hW2, const float* __restrict__ hb2,
                       float* __restrict__ out) {
    int b = blockIdx.x, j = threadIdx.x;   // 128 threads
    __shared__ float p[128];
    __shared__ float hh[64];
    float s = 0.f;
    for (int t = 0; t < 64; t++) s += g_seq[(b * 64 + t) * 128 + j];
    p[j] = s * (1.0f / 64.0f);
    __syncthreads();
    if (j < 64) {
        float a = hb1[j];
        #pragma unroll
        for (int k = 0; k < 128; k++) a += p[k] * hW1[j * 128 + k];
        hh[j] = fmaxf(a, 0.f);
    }
    __syncthreads();
    if (j < 2) {
        float o = hb2[j];
        #pragma unroll
        for (int k = 0; k < 64; k++) o += hh[k] * hW2[j * 64 + k];
        out[b * 2 + j] = o;
    }
}

// ---------------- host launcher ----------------
extern "C" void kernel_launch(void* const* d_in, const int* in_sizes, int n_in,
                              void* d_out, int out_size) {
    const float* x     = (const float*)d_in[0];
    const int*   esrc  = (const int*)d_in[1];
    const int*   edst  = (const int*)d_in[2];
    const float* gW1   = (const float*)d_in[4];
    const float* gb1   = (const float*)d_in[5];
    const float* ln1g  = (const float*)d_in[6];
    const float* ln1b  = (const float*)d_in[7];
    const float* gW2   = (const float*)d_in[8];
    const float* gb2   = (const float*)d_in[9];
    const float* ln2g  = (const float*)d_in[10];
    const float* ln2b  = (const float*)d_in[11];
    const float* gW3   = (const float*)d_in[12];
    const float* gb3   = (const float*)d_in[13];
    const float* tWqkv = (const float*)d_in[14];
    const float* tbqkv = (const float*)d_in[15];
    const float* tWo   = (const float*)d_in[16];
    const float* tbo   = (const float*)d_in[17];
    const float* tg1   = (const float*)d_in[18];
    const float* tb1   = (const float*)d_in[19];
    const float* tg2   = (const float*)d_in[20];
    const float* tb2   = (const float*)d_in[21];
    const float* tWf1  = (const float*)d_in[22];
    const float* tbf1  = (const float*)d_in[23];
    const float* tWf2  = (const float*)d_in[24];
    const float* tbf2  = (const float*)d_in[25];
    const float* hW1   = (const float*)d_in[26];
    const float* hb1   = (const float*)d_in[27];
    const float* hW2   = (const float*)d_in[28];
    const float* hb2   = (const float*)d_in[29];

    float *p_seq, *p_qkv, *p_att, *p_proj, *p_ffn;
    cudaGetSymbolAddress((void**)&p_seq,  g_seq);
    cudaGetSymbolAddress((void**)&p_qkv,  g_qkv);
    cudaGetSymbolAddress((void**)&p_att,  g_att);
    cudaGetSymbolAddress((void**)&p_proj, g_proj);
    cudaGetSymbolAddress((void**)&p_ffn,  g_ffn);

    // degree / dinv
    k_deg_init<<<N_NODES / 256, 256>>>();
    k_deg_acc<<<N_EDGES / 256, 256>>>(edst);
    k_rsqrt<<<N_NODES / 256, 256>>>();

    // GCN layer 1
    k_agg1_init<<<N_NODES / 256, 256>>>(x);
    k_agg1_edges<<<N_EDGES / 256, 256>>>(x, esrc, edst);
    k_l1<<<N_NODES / 4, 256>>>(gW1, gb1, ln1g, ln1b);

    // GCN layer 2
    k_selfinit<<<N_NODES * 16 / 256, 256>>>();
    k_edges64<<<N_EDGES * 16 / 256, 256>>>(esrc, edst);
    k_l2<<<N_NODES / 16, 256>>>(gW2, gb2, ln2g, ln2b);

    // GCN layer 3 (aggregation only; transform fused into readout)
    k_selfinit<<<N_NODES * 16 / 256, 256>>>();
    k_edges64<<<N_EDGES * 16 / 256, 256>>>(esrc, edst);

    // readout + positional encoding
    k_graph_emb<<<N_GRAPH, 128>>>(gW3, gb3);

    // transformer
    dim3 thr(16, 16);
    for (int l = 0; l < NL; l++) {
        k_gemm<<<dim3(384 / 64, 512 / 64), thr>>>(p_seq, tWqkv + l * 384 * 128,
                                                  tbqkv + l * 384, p_qkv, 512, 384, 128, 0);
        k_attn<<<BB * NH, 64>>>();
        k_gemm<<<dim3(128 / 64, 512 / 64), thr>>>(p_att, tWo + l * 128 * 128,
                                                  tbo + l * 128, p_proj, 512, 128, 128, 0);
        k_addln<<<512, 128>>>(tg1 + l * 128, tb1 + l * 128);
        k_gemm<<<dim3(512 / 64, 512 / 64), thr>>>(p_seq, tWf1 + l * 512 * 128,
                                                  tbf1 + l * 512, p_ffn, 512, 512, 128, 1);
        k_gemm<<<dim3(128 / 64, 512 / 64), thr>>>(p_ffn, tWf2 + l * 128 * 512,
                                                  tbf2 + l * 128, p_proj, 512, 128, 512, 0);
        k_addln<<<512, 128>>>(tg2 + l * 128, tb2 + l * 128);
    }

    // head
    k_head<<<BB, 128>>>(hW1, hb1, hW2, hb2, (float*)d_out);
}